// round 15
// baseline (speedup 1.0000x reference)
#include <cuda_runtime.h>
#include <cuda_fp16.h>
#include <cstdint>

#define BB   32
#define SS   512
#define HH   768
#define VV   8192
#define WMAX 256
#define MM   (BB * WMAX)       // 8192

__device__ __align__(16) __half g_a[(size_t)MM * HH];
__device__ __align__(16) __half g_w[(size_t)HH * VV];

// ---------------------------------------------------------------------------
// PTX helpers — family-portable (sm_80+)
// ---------------------------------------------------------------------------
__device__ __forceinline__ uint32_t smem_u32(const void* p) {
    uint32_t a;
    asm("{ .reg .u64 t; cvta.to.shared.u64 t, %1; cvt.u32.u64 %0, t; }" : "=r"(a) : "l"(p));
    return a;
}
__device__ __forceinline__ void cp16(uint32_t s, const void* g) {
    asm volatile("cp.async.cg.shared.global [%0], [%1], 16;" :: "r"(s), "l"(g));
}
__device__ __forceinline__ void ldsm4(uint32_t* r, uint32_t addr) {
    asm volatile("ldmatrix.sync.aligned.m8n8.x4.shared.b16 {%0,%1,%2,%3}, [%4];"
                 : "=r"(r[0]), "=r"(r[1]), "=r"(r[2]), "=r"(r[3]) : "r"(addr));
}
__device__ __forceinline__ void ldsm4t(uint32_t* r, uint32_t addr) {
    asm volatile("ldmatrix.sync.aligned.m8n8.x4.trans.shared.b16 {%0,%1,%2,%3}, [%4];"
                 : "=r"(r[0]), "=r"(r[1]), "=r"(r[2]), "=r"(r[3]) : "r"(addr));
}
__device__ __forceinline__ void mma_f16(float* d, const uint32_t* a, const uint32_t* b) {
    asm volatile(
        "mma.sync.aligned.m16n8k16.row.col.f32.f16.f16.f32 "
        "{%0,%1,%2,%3}, {%4,%5,%6,%7}, {%8,%9}, {%0,%1,%2,%3};"
        : "+f"(d[0]), "+f"(d[1]), "+f"(d[2]), "+f"(d[3])
        : "r"(a[0]), "r"(a[1]), "r"(a[2]), "r"(a[3]), "r"(b[0]), "r"(b[1]));
}
__device__ __forceinline__ float4 ldcs4(const float* p) {
    float4 v;
    asm volatile("ld.global.cs.v4.f32 {%0,%1,%2,%3}, [%4];"
                 : "=f"(v.x), "=f"(v.y), "=f"(v.z), "=f"(v.w) : "l"(p));
    return v;
}

// ---------------------------------------------------------------------------
// Fused prep. Blocks [0, SEG_BLOCKS): segment-mean WPB=8, 192 threads.
// Blocks [SEG_BLOCKS, ...): W fp32 -> fp16, 32B per thread, streaming loads.
// ---------------------------------------------------------------------------
#define WPB        8
#define SEG_BLOCKS ((WMAX / WPB) * BB)                    // 1024
#define WC_TOTAL8  ((size_t)HH * VV / 8)                  // 786432 (8 floats/thread)
#define WC_BLOCKS  ((unsigned)((WC_TOTAL8 + 191) / 192))  // 4096

__global__ __launch_bounds__(192)
void prep_kernel(const float* __restrict__ enc,
                 const int*   __restrict__ ids,
                 const float* __restrict__ W) {
    const int tid = threadIdx.x;

    if (blockIdx.x >= SEG_BLOCKS) {
        size_t idx = (size_t)(blockIdx.x - SEG_BLOCKS) * 192 + tid;
        if (idx < WC_TOTAL8) {
            float4 v0 = ldcs4(W + idx * 8);
            float4 v1 = ldcs4(W + idx * 8 + 4);
            __half2* p = reinterpret_cast<__half2*>(g_w) + idx * 4;
            p[0] = __halves2half2(__float2half_rn(v0.x), __float2half_rn(v0.y));
            p[1] = __halves2half2(__float2half_rn(v0.z), __float2half_rn(v0.w));
            p[2] = __halves2half2(__float2half_rn(v1.x), __float2half_rn(v1.y));
            p[3] = __halves2half2(__float2half_rn(v1.z), __float2half_rn(v1.w));
        }
        return;
    }

    __shared__ int srow[SS];
    const int b  = blockIdx.x / (WMAX / WPB);
    const int w0 = (blockIdx.x % (WMAX / WPB)) * WPB;

    for (int i = tid; i < SS; i += 192) srow[i] = ids[b * SS + i];
    __syncthreads();

    int lo = 0, r = SS;
    while (lo < r) { int m = (lo + r) >> 1; if (srow[m] < w0) lo = m + 1; else r = m; }
    int hi = lo; r = SS;
    while (hi < r) { int m = (hi + r) >> 1; if (srow[m] < w0 + WPB) hi = m + 1; else r = m; }

    const float* base = enc + (size_t)b * SS * HH + tid * 4;
    const size_t obase = (size_t)(b * WMAX) * HH + tid * 4;

    unsigned present = 0;
    int t = lo;
    while (t < hi) {
        const int w = srow[t];
        int e = t + 1;
        while (e < hi && srow[e] == w) ++e;

        float4 s0 = make_float4(0.f, 0.f, 0.f, 0.f);
        float4 s1 = make_float4(0.f, 0.f, 0.f, 0.f);
        float4 s2 = make_float4(0.f, 0.f, 0.f, 0.f);
        float4 s3 = make_float4(0.f, 0.f, 0.f, 0.f);
        int u = t;
        for (; u + 3 < e; u += 4) {
            float4 v0 = ldcs4(base + (size_t)u * HH);
            float4 v1 = ldcs4(base + (size_t)(u + 1) * HH);
            float4 v2 = ldcs4(base + (size_t)(u + 2) * HH);
            float4 v3 = ldcs4(base + (size_t)(u + 3) * HH);
            s0.x += v0.x; s0.y += v0.y; s0.z += v0.z; s0.w += v0.w;
            s1.x += v1.x; s1.y += v1.y; s1.z += v1.z; s1.w += v1.w;
            s2.x += v2.x; s2.y += v2.y; s2.z += v2.z; s2.w += v2.w;
            s3.x += v3.x; s3.y += v3.y; s3.z += v3.z; s3.w += v3.w;
        }
        for (; u < e; ++u) {
            float4 v0 = ldcs4(base + (size_t)u * HH);
            s0.x += v0.x; s0.y += v0.y; s0.z += v0.z; s0.w += v0.w;
        }
        const float inv = 1.0f / (float)(e - t);
        __half2* p = reinterpret_cast<__half2*>(g_a + obase + (size_t)w * HH);
        p[0] = __halves2half2(__float2half_rn((s0.x + s1.x + s2.x + s3.x) * inv),
                              __float2half_rn((s0.y + s1.y + s2.y + s3.y) * inv));
        p[1] = __halves2half2(__float2half_rn((s0.z + s1.z + s2.z + s3.z) * inv),
                              __float2half_rn((s0.w + s1.w + s2.w + s3.w) * inv));
        present |= 1u << (w - w0);
        t = e;
    }
#pragma unroll
    for (int wl = 0; wl < WPB; ++wl) {
        if (!(present & (1u << wl))) {
            __half2 z = __halves2half2(__float2half_rn(0.f), __float2half_rn(0.f));
            __half2* p = reinterpret_cast<__half2*>(g_a + obase + (size_t)(w0 + wl) * HH);
            p[0] = z; p[1] = z;
        }
    }
}

// ---------------------------------------------------------------------------
// HMMA GEMM (R14 + hoisted next-stage cp.async).
// CTA 128x128, BK=32, 4-stage cp.async, 8 warps (2x4), warp tile 64x32.
// 2 CTAs / SM (64 KB smem each, <=128 regs) = 16 warps/SM.
// ---------------------------------------------------------------------------
#define BM 128
#define BN 128
#define BK 32
#define KTILES   (HH / BK)     // 24
#define STAGES   4
#define OFF_A    0             // [128][32] fp16 = 8 KB (64B rows)
#define OFF_B    8192          // [32][128] fp16 = 8 KB (256B rows)
#define STAGE_B  16384
#define SMEM_TOTAL (STAGES * STAGE_B)   // 65536

__device__ __forceinline__ uint32_t swA(uint32_t off) { return off ^ ((off >> 3) & 0x30); }
__device__ __forceinline__ uint32_t swB(uint32_t off) { return off ^ ((off >> 4) & 0x70); }

__global__ __launch_bounds__(256, 2)
void mma_gemm_kernel(const float* __restrict__ bias, float* __restrict__ C) {
    extern __shared__ char smem[];
    const uint32_t sb = smem_u32(smem);
    const int tid  = threadIdx.x;
    const int lane = tid & 31;
    const int wid  = tid >> 5;
    const int bm = blockIdx.y * BM;
    const int bn = blockIdx.x * BN;
    const int wm = (wid >> 2) * 64;   // 0 / 64
    const int wn = (wid & 3) * 32;    // 0..96

    float acc[4][4][4];
#pragma unroll
    for (int i = 0; i < 4; ++i)
#pragma unroll
        for (int j = 0; j < 4; ++j)
#pragma unroll
            for (int q = 0; q < 4; ++q) acc[i][j][q] = 0.0f;

    auto load_stage = [&](int slot, int kt) {
        const uint32_t st = sb + slot * STAGE_B;
        const size_t ka = (size_t)kt * BK;
#pragma unroll
        for (int it = 0; it < 2; ++it) {
            int p = tid + it * 256;
            int m = p >> 2, u = p & 3;
            cp16(st + OFF_A + swA((uint32_t)m * 64 + u * 16),
                 g_a + (size_t)(bm + m) * HH + ka + u * 8);
        }
#pragma unroll
        for (int it = 0; it < 2; ++it) {
            int p = tid + it * 256;
            int k = p >> 4, u = p & 15;
            cp16(st + OFF_B + swB((uint32_t)k * 256 + u * 16),
                 g_w + (size_t)(ka + k) * VV + bn + u * 8);
        }
        asm volatile("cp.async.commit_group;");
    };

#pragma unroll
    for (int s = 0; s < STAGES - 1; ++s) load_stage(s, s);

    for (int kt = 0; kt < KTILES; ++kt) {
        asm volatile("cp.async.wait_group 2;");
        __syncthreads();
        const uint32_t st = sb + (kt & (STAGES - 1)) * STAGE_B;

        // hoisted: issue next stage's async loads before compute
        if (kt + STAGES - 1 < KTILES)
            load_stage((kt + STAGES - 1) & (STAGES - 1), kt + STAGES - 1);
        else
            asm volatile("cp.async.commit_group;");

#pragma unroll
        for (int h = 0; h < 2; ++h) {
            const int k16 = h * 16;
            uint32_t af[4][4];
            uint32_t bf[2][4];
            // first mma (af[0], bf[0]) operands first, then the rest
            {
                uint32_t row = wm + 0 * 16 + (lane & 15);
                uint32_t u = (uint32_t)(k16 >> 3) + (lane >> 4);
                ldsm4(af[0], st + OFF_A + swA(row * 64 + u * 16));
            }
            {
                uint32_t bk = (uint32_t)k16 + (lane & 15);
                uint32_t u = (uint32_t)(wn >> 3) + (lane >> 4);
                ldsm4t(bf[0], st + OFF_B + swB(bk * 256 + u * 16));
                ldsm4t(bf[1], st + OFF_B + swB(bk * 256 + u * 16 + 32));
            }
#pragma unroll
            for (int i = 1; i < 4; ++i) {
                uint32_t row = wm + i * 16 + (lane & 15);
                uint32_t u = (uint32_t)(k16 >> 3) + (lane >> 4);
                ldsm4(af[i], st + OFF_A + swA(row * 64 + u * 16));
            }
#pragma unroll
            for (int i = 0; i < 4; ++i) {
                mma_f16(acc[i][0], af[i], bf[0]);
                mma_f16(acc[i][1], af[i], bf[0] + 2);
                mma_f16(acc[i][2], af[i], bf[1]);
                mma_f16(acc[i][3], af[i], bf[1] + 2);
            }
        }
    }

    // ---- epilogue: bias + store ----
    const int rbase = bm + wm + (lane >> 2);
    const int cbase = bn + wn + (lane & 3) * 2;
#pragma unroll
    for (int j = 0; j < 4; ++j) {
        const int c = cbase + j * 8;
        const float bx = __ldg(&bias[c]);
        const float by = __ldg(&bias[c + 1]);
#pragma unroll
        for (int i = 0; i < 4; ++i) {
            const int r = rbase + i * 16;
            float2 v0 = make_float2(acc[i][j][0] + bx, acc[i][j][1] + by);
            float2 v1 = make_float2(acc[i][j][2] + bx, acc[i][j][3] + by);
            *reinterpret_cast<float2*>(&C[(size_t)r * VV + c]) = v0;
            *reinterpret_cast<float2*>(&C[(size_t)(r + 8) * VV + c]) = v1;
        }
    }
}

// ---------------------------------------------------------------------------
// Launch
// ---------------------------------------------------------------------------
extern "C" void kernel_launch(void* const* d_in, const int* in_sizes, int n_in,
                              void* d_out, int out_size) {
    const float* enc  = (const float*)d_in[0];   // [32,512,768]
    const int*   ids  = (const int*)  d_in[1];   // [32,512]
    const float* W    = (const float*)d_in[2];   // [768,8192]
    const float* bias = (const float*)d_in[3];   // [8192]
    float* out = (float*)d_out;                  // [32,256,8192]

    prep_kernel<<<SEG_BLOCKS + WC_BLOCKS, 192>>>(enc, ids, W);

    cudaFuncSetAttribute(mma_gemm_kernel,
                         cudaFuncAttributeMaxDynamicSharedMemorySize, SMEM_TOTAL);
    mma_gemm_kernel<<<dim3(VV / BN, MM / BM), 256, SMEM_TOTAL>>>(bias, out);
}

// round 16
// speedup vs baseline: 1.0506x; 1.0506x over previous
#include <cuda_runtime.h>
#include <cuda_fp16.h>
#include <cstdint>

#define BB   32
#define SS   512
#define HH   768
#define VV   8192
#define WMAX 256
#define MM   (BB * WMAX)       // 8192

__device__ __align__(16) __half g_a[(size_t)MM * HH];
__device__ __align__(16) __half g_w[(size_t)HH * VV];

// ---------------------------------------------------------------------------
// PTX helpers — family-portable (sm_80+)
// ---------------------------------------------------------------------------
__device__ __forceinline__ uint32_t smem_u32(const void* p) {
    uint32_t a;
    asm("{ .reg .u64 t; cvta.to.shared.u64 t, %1; cvt.u32.u64 %0, t; }" : "=r"(a) : "l"(p));
    return a;
}
__device__ __forceinline__ void cp16(uint32_t s, const void* g) {
    asm volatile("cp.async.cg.shared.global [%0], [%1], 16;" :: "r"(s), "l"(g));
}
__device__ __forceinline__ void ldsm4(uint32_t* r, uint32_t addr) {
    asm volatile("ldmatrix.sync.aligned.m8n8.x4.shared.b16 {%0,%1,%2,%3}, [%4];"
                 : "=r"(r[0]), "=r"(r[1]), "=r"(r[2]), "=r"(r[3]) : "r"(addr));
}
__device__ __forceinline__ void ldsm4t(uint32_t* r, uint32_t addr) {
    asm volatile("ldmatrix.sync.aligned.m8n8.x4.trans.shared.b16 {%0,%1,%2,%3}, [%4];"
                 : "=r"(r[0]), "=r"(r[1]), "=r"(r[2]), "=r"(r[3]) : "r"(addr));
}
__device__ __forceinline__ void mma_f16(float* d, const uint32_t* a, const uint32_t* b) {
    asm volatile(
        "mma.sync.aligned.m16n8k16.row.col.f32.f16.f16.f32 "
        "{%0,%1,%2,%3}, {%4,%5,%6,%7}, {%8,%9}, {%0,%1,%2,%3};"
        : "+f"(d[0]), "+f"(d[1]), "+f"(d[2]), "+f"(d[3])
        : "r"(a[0]), "r"(a[1]), "r"(a[2]), "r"(a[3]), "r"(b[0]), "r"(b[1]));
}
__device__ __forceinline__ float4 ldcs4(const float* p) {
    float4 v;
    asm volatile("ld.global.cs.v4.f32 {%0,%1,%2,%3}, [%4];"
                 : "=f"(v.x), "=f"(v.y), "=f"(v.z), "=f"(v.w) : "l"(p));
    return v;
}
__device__ __forceinline__ void stcs2(float* p, float2 v) {
    asm volatile("st.global.cs.v2.f32 [%0], {%1,%2};" :: "l"(p), "f"(v.x), "f"(v.y));
}

// ---------------------------------------------------------------------------
// Fused prep (R15). Blocks [0, SEG_BLOCKS): segment-mean WPB=8, 192 threads.
// Blocks [SEG_BLOCKS, ...): W fp32 -> fp16, 32B per thread, streaming loads.
// ---------------------------------------------------------------------------
#define WPB        8
#define SEG_BLOCKS ((WMAX / WPB) * BB)                    // 1024
#define WC_TOTAL8  ((size_t)HH * VV / 8)                  // 786432
#define WC_BLOCKS  ((unsigned)((WC_TOTAL8 + 191) / 192))  // 4096

__global__ __launch_bounds__(192)
void prep_kernel(const float* __restrict__ enc,
                 const int*   __restrict__ ids,
                 const float* __restrict__ W) {
    const int tid = threadIdx.x;

    if (blockIdx.x >= SEG_BLOCKS) {
        size_t idx = (size_t)(blockIdx.x - SEG_BLOCKS) * 192 + tid;
        if (idx < WC_TOTAL8) {
            float4 v0 = ldcs4(W + idx * 8);
            float4 v1 = ldcs4(W + idx * 8 + 4);
            __half2* p = reinterpret_cast<__half2*>(g_w) + idx * 4;
            p[0] = __halves2half2(__float2half_rn(v0.x), __float2half_rn(v0.y));
            p[1] = __halves2half2(__float2half_rn(v0.z), __float2half_rn(v0.w));
            p[2] = __halves2half2(__float2half_rn(v1.x), __float2half_rn(v1.y));
            p[3] = __halves2half2(__float2half_rn(v1.z), __float2half_rn(v1.w));
        }
        return;
    }

    __shared__ int srow[SS];
    const int b  = blockIdx.x / (WMAX / WPB);
    const int w0 = (blockIdx.x % (WMAX / WPB)) * WPB;

    for (int i = tid; i < SS; i += 192) srow[i] = ids[b * SS + i];
    __syncthreads();

    int lo = 0, r = SS;
    while (lo < r) { int m = (lo + r) >> 1; if (srow[m] < w0) lo = m + 1; else r = m; }
    int hi = lo; r = SS;
    while (hi < r) { int m = (hi + r) >> 1; if (srow[m] < w0 + WPB) hi = m + 1; else r = m; }

    const float* base = enc + (size_t)b * SS * HH + tid * 4;
    const size_t obase = (size_t)(b * WMAX) * HH + tid * 4;

    unsigned present = 0;
    int t = lo;
    while (t < hi) {
        const int w = srow[t];
        int e = t + 1;
        while (e < hi && srow[e] == w) ++e;

        float4 s0 = make_float4(0.f, 0.f, 0.f, 0.f);
        float4 s1 = make_float4(0.f, 0.f, 0.f, 0.f);
        float4 s2 = make_float4(0.f, 0.f, 0.f, 0.f);
        float4 s3 = make_float4(0.f, 0.f, 0.f, 0.f);
        int u = t;
        for (; u + 3 < e; u += 4) {
            float4 v0 = ldcs4(base + (size_t)u * HH);
            float4 v1 = ldcs4(base + (size_t)(u + 1) * HH);
            float4 v2 = ldcs4(base + (size_t)(u + 2) * HH);
            float4 v3 = ldcs4(base + (size_t)(u + 3) * HH);
            s0.x += v0.x; s0.y += v0.y; s0.z += v0.z; s0.w += v0.w;
            s1.x += v1.x; s1.y += v1.y; s1.z += v1.z; s1.w += v1.w;
            s2.x += v2.x; s2.y += v2.y; s2.z += v2.z; s2.w += v2.w;
            s3.x += v3.x; s3.y += v3.y; s3.z += v3.z; s3.w += v3.w;
        }
        for (; u < e; ++u) {
            float4 v0 = ldcs4(base + (size_t)u * HH);
            s0.x += v0.x; s0.y += v0.y; s0.z += v0.z; s0.w += v0.w;
        }
        const float inv = 1.0f / (float)(e - t);
        __half2* p = reinterpret_cast<__half2*>(g_a + obase + (size_t)w * HH);
        p[0] = __halves2half2(__float2half_rn((s0.x + s1.x + s2.x + s3.x) * inv),
                              __float2half_rn((s0.y + s1.y + s2.y + s3.y) * inv));
        p[1] = __halves2half2(__float2half_rn((s0.z + s1.z + s2.z + s3.z) * inv),
                              __float2half_rn((s0.w + s1.w + s2.w + s3.w) * inv));
        present |= 1u << (w - w0);
        t = e;
    }
#pragma unroll
    for (int wl = 0; wl < WPB; ++wl) {
        if (!(present & (1u << wl))) {
            __half2 z = __halves2half2(__float2half_rn(0.f), __float2half_rn(0.f));
            __half2* p = reinterpret_cast<__half2*>(g_a + obase + (size_t)(w0 + wl) * HH);
            p[0] = z; p[1] = z;
        }
    }
}

// ---------------------------------------------------------------------------
// HMMA GEMM (R14 exact: tail-placed next-stage load, first-mma-first ldsm)
// + streaming epilogue stores.
// CTA 128x128, BK=32, 4-stage cp.async, 8 warps (2x4), warp tile 64x32.
// 2 CTAs / SM (64 KB smem each, <=128 regs) = 16 warps/SM.
// ---------------------------------------------------------------------------
#define BM 128
#define BN 128
#define BK 32
#define KTILES   (HH / BK)     // 24
#define STAGES   4
#define OFF_A    0             // [128][32] fp16 = 8 KB (64B rows)
#define OFF_B    8192          // [32][128] fp16 = 8 KB (256B rows)
#define STAGE_B  16384
#define SMEM_TOTAL (STAGES * STAGE_B)   // 65536

__device__ __forceinline__ uint32_t swA(uint32_t off) { return off ^ ((off >> 3) & 0x30); }
__device__ __forceinline__ uint32_t swB(uint32_t off) { return off ^ ((off >> 4) & 0x70); }

__global__ __launch_bounds__(256, 2)
void mma_gemm_kernel(const float* __restrict__ bias, float* __restrict__ C) {
    extern __shared__ char smem[];
    const uint32_t sb = smem_u32(smem);
    const int tid  = threadIdx.x;
    const int lane = tid & 31;
    const int wid  = tid >> 5;
    const int bm = blockIdx.y * BM;
    const int bn = blockIdx.x * BN;
    const int wm = (wid >> 2) * 64;   // 0 / 64
    const int wn = (wid & 3) * 32;    // 0..96

    float acc[4][4][4];
#pragma unroll
    for (int i = 0; i < 4; ++i)
#pragma unroll
        for (int j = 0; j < 4; ++j)
#pragma unroll
            for (int q = 0; q < 4; ++q) acc[i][j][q] = 0.0f;

    auto load_stage = [&](int slot, int kt) {
        const uint32_t st = sb + slot * STAGE_B;
        const size_t ka = (size_t)kt * BK;
#pragma unroll
        for (int it = 0; it < 2; ++it) {
            int p = tid + it * 256;
            int m = p >> 2, u = p & 3;
            cp16(st + OFF_A + swA((uint32_t)m * 64 + u * 16),
                 g_a + (size_t)(bm + m) * HH + ka + u * 8);
        }
#pragma unroll
        for (int it = 0; it < 2; ++it) {
            int p = tid + it * 256;
            int k = p >> 4, u = p & 15;
            cp16(st + OFF_B + swB((uint32_t)k * 256 + u * 16),
                 g_w + (size_t)(ka + k) * VV + bn + u * 8);
        }
        asm volatile("cp.async.commit_group;");
    };

#pragma unroll
    for (int s = 0; s < STAGES - 1; ++s) load_stage(s, s);

    for (int kt = 0; kt < KTILES; ++kt) {
        asm volatile("cp.async.wait_group 2;");
        __syncthreads();
        const uint32_t st = sb + (kt & (STAGES - 1)) * STAGE_B;

#pragma unroll
        for (int h = 0; h < 2; ++h) {
            const int k16 = h * 16;
            uint32_t af[4][4];
            uint32_t bf[2][4];
            // first mma (af[0], bf[0]) operands first, then the rest
            {
                uint32_t row = wm + 0 * 16 + (lane & 15);
                uint32_t u = (uint32_t)(k16 >> 3) + (lane >> 4);
                ldsm4(af[0], st + OFF_A + swA(row * 64 + u * 16));
            }
            {
                uint32_t bk = (uint32_t)k16 + (lane & 15);
                uint32_t u = (uint32_t)(wn >> 3) + (lane >> 4);
                ldsm4t(bf[0], st + OFF_B + swB(bk * 256 + u * 16));
                ldsm4t(bf[1], st + OFF_B + swB(bk * 256 + u * 16 + 32));
            }
#pragma unroll
            for (int i = 1; i < 4; ++i) {
                uint32_t row = wm + i * 16 + (lane & 15);
                uint32_t u = (uint32_t)(k16 >> 3) + (lane >> 4);
                ldsm4(af[i], st + OFF_A + swA(row * 64 + u * 16));
            }
#pragma unroll
            for (int i = 0; i < 4; ++i) {
                mma_f16(acc[i][0], af[i], bf[0]);
                mma_f16(acc[i][1], af[i], bf[0] + 2);
                mma_f16(acc[i][2], af[i], bf[1]);
                mma_f16(acc[i][3], af[i], bf[1] + 2);
            }
        }
        if (kt + STAGES - 1 < KTILES)
            load_stage((kt + STAGES - 1) & (STAGES - 1), kt + STAGES - 1);
        else
            asm volatile("cp.async.commit_group;");
    }

    // ---- epilogue: bias + streaming store (evict-first, keep L2 for A/W) ----
    const int rbase = bm + wm + (lane >> 2);
    const int cbase = bn + wn + (lane & 3) * 2;
#pragma unroll
    for (int j = 0; j < 4; ++j) {
        const int c = cbase + j * 8;
        const float bx = __ldg(&bias[c]);
        const float by = __ldg(&bias[c + 1]);
#pragma unroll
        for (int i = 0; i < 4; ++i) {
            const int r = rbase + i * 16;
            stcs2(&C[(size_t)r * VV + c],
                  make_float2(acc[i][j][0] + bx, acc[i][j][1] + by));
            stcs2(&C[(size_t)(r + 8) * VV + c],
                  make_float2(acc[i][j][2] + bx, acc[i][j][3] + by));
        }
    }
}

// ---------------------------------------------------------------------------
// Launch
// ---------------------------------------------------------------------------
extern "C" void kernel_launch(void* const* d_in, const int* in_sizes, int n_in,
                              void* d_out, int out_size) {
    const float* enc  = (const float*)d_in[0];   // [32,512,768]
    const int*   ids  = (const int*)  d_in[1];   // [32,512]
    const float* W    = (const float*)d_in[2];   // [768,8192]
    const float* bias = (const float*)d_in[3];   // [8192]
    float* out = (float*)d_out;                  // [32,256,8192]

    prep_kernel<<<SEG_BLOCKS + WC_BLOCKS, 192>>>(enc, ids, W);

    cudaFuncSetAttribute(mma_gemm_kernel,
                         cudaFuncAttributeMaxDynamicSharedMemorySize, SMEM_TOTAL);
    mma_gemm_kernel<<<dim3(VV / BN, MM / BM), 256, SMEM_TOTAL>>>(bias, out);
}

// round 17
// speedup vs baseline: 1.0596x; 1.0086x over previous
#include <cuda_runtime.h>
#include <cuda_fp16.h>
#include <cstdint>

#define BB   32
#define SS   512
#define HH   768
#define VV   8192
#define WMAX 256
#define MM   (BB * WMAX)       // 8192

__device__ __align__(16) __half g_a[(size_t)MM * HH];
__device__ __align__(16) __half g_w[(size_t)HH * VV];

// ---------------------------------------------------------------------------
// PTX helpers — family-portable (sm_80+)
// ---------------------------------------------------------------------------
__device__ __forceinline__ uint32_t smem_u32(const void* p) {
    uint32_t a;
    asm("{ .reg .u64 t; cvta.to.shared.u64 t, %1; cvt.u32.u64 %0, t; }" : "=r"(a) : "l"(p));
    return a;
}
__device__ __forceinline__ void cp16(uint32_t s, const void* g) {
    asm volatile("cp.async.cg.shared.global [%0], [%1], 16;" :: "r"(s), "l"(g));
}
__device__ __forceinline__ void ldsm4(uint32_t* r, uint32_t addr) {
    asm volatile("ldmatrix.sync.aligned.m8n8.x4.shared.b16 {%0,%1,%2,%3}, [%4];"
                 : "=r"(r[0]), "=r"(r[1]), "=r"(r[2]), "=r"(r[3]) : "r"(addr));
}
__device__ __forceinline__ void ldsm4t(uint32_t* r, uint32_t addr) {
    asm volatile("ldmatrix.sync.aligned.m8n8.x4.trans.shared.b16 {%0,%1,%2,%3}, [%4];"
                 : "=r"(r[0]), "=r"(r[1]), "=r"(r[2]), "=r"(r[3]) : "r"(addr));
}
__device__ __forceinline__ void mma_f16(float* d, const uint32_t* a, const uint32_t* b) {
    asm volatile(
        "mma.sync.aligned.m16n8k16.row.col.f32.f16.f16.f32 "
        "{%0,%1,%2,%3}, {%4,%5,%6,%7}, {%8,%9}, {%0,%1,%2,%3};"
        : "+f"(d[0]), "+f"(d[1]), "+f"(d[2]), "+f"(d[3])
        : "r"(a[0]), "r"(a[1]), "r"(a[2]), "r"(a[3]), "r"(b[0]), "r"(b[1]));
}
__device__ __forceinline__ float4 ldcs4(const float* p) {
    float4 v;
    asm volatile("ld.global.cs.v4.f32 {%0,%1,%2,%3}, [%4];"
                 : "=f"(v.x), "=f"(v.y), "=f"(v.z), "=f"(v.w) : "l"(p));
    return v;
}
__device__ __forceinline__ void stcs2(float* p, float2 v) {
    asm volatile("st.global.cs.v2.f32 [%0], {%1,%2};" :: "l"(p), "f"(v.x), "f"(v.y));
}

// ---------------------------------------------------------------------------
// Fused prep (R16 exact). Blocks [0, SEG_BLOCKS): segment-mean WPB=8.
// Blocks [SEG_BLOCKS, ...): W fp32 -> fp16, 32B per thread, streaming loads.
// ---------------------------------------------------------------------------
#define WPB        8
#define SEG_BLOCKS ((WMAX / WPB) * BB)                    // 1024
#define WC_TOTAL8  ((size_t)HH * VV / 8)                  // 786432
#define WC_BLOCKS  ((unsigned)((WC_TOTAL8 + 191) / 192))  // 4096

__global__ __launch_bounds__(192)
void prep_kernel(const float* __restrict__ enc,
                 const int*   __restrict__ ids,
                 const float* __restrict__ W) {
    const int tid = threadIdx.x;

    if (blockIdx.x >= SEG_BLOCKS) {
        size_t idx = (size_t)(blockIdx.x - SEG_BLOCKS) * 192 + tid;
        if (idx < WC_TOTAL8) {
            float4 v0 = ldcs4(W + idx * 8);
            float4 v1 = ldcs4(W + idx * 8 + 4);
            __half2* p = reinterpret_cast<__half2*>(g_w) + idx * 4;
            p[0] = __halves2half2(__float2half_rn(v0.x), __float2half_rn(v0.y));
            p[1] = __halves2half2(__float2half_rn(v0.z), __float2half_rn(v0.w));
            p[2] = __halves2half2(__float2half_rn(v1.x), __float2half_rn(v1.y));
            p[3] = __halves2half2(__float2half_rn(v1.z), __float2half_rn(v1.w));
        }
        return;
    }

    __shared__ int srow[SS];
    const int b  = blockIdx.x / (WMAX / WPB);
    const int w0 = (blockIdx.x % (WMAX / WPB)) * WPB;

    for (int i = tid; i < SS; i += 192) srow[i] = ids[b * SS + i];
    __syncthreads();

    int lo = 0, r = SS;
    while (lo < r) { int m = (lo + r) >> 1; if (srow[m] < w0) lo = m + 1; else r = m; }
    int hi = lo; r = SS;
    while (hi < r) { int m = (hi + r) >> 1; if (srow[m] < w0 + WPB) hi = m + 1; else r = m; }

    const float* base = enc + (size_t)b * SS * HH + tid * 4;
    const size_t obase = (size_t)(b * WMAX) * HH + tid * 4;

    unsigned present = 0;
    int t = lo;
    while (t < hi) {
        const int w = srow[t];
        int e = t + 1;
        while (e < hi && srow[e] == w) ++e;

        float4 s0 = make_float4(0.f, 0.f, 0.f, 0.f);
        float4 s1 = make_float4(0.f, 0.f, 0.f, 0.f);
        float4 s2 = make_float4(0.f, 0.f, 0.f, 0.f);
        float4 s3 = make_float4(0.f, 0.f, 0.f, 0.f);
        int u = t;
        for (; u + 3 < e; u += 4) {
            float4 v0 = ldcs4(base + (size_t)u * HH);
            float4 v1 = ldcs4(base + (size_t)(u + 1) * HH);
            float4 v2 = ldcs4(base + (size_t)(u + 2) * HH);
            float4 v3 = ldcs4(base + (size_t)(u + 3) * HH);
            s0.x += v0.x; s0.y += v0.y; s0.z += v0.z; s0.w += v0.w;
            s1.x += v1.x; s1.y += v1.y; s1.z += v1.z; s1.w += v1.w;
            s2.x += v2.x; s2.y += v2.y; s2.z += v2.z; s2.w += v2.w;
            s3.x += v3.x; s3.y += v3.y; s3.z += v3.z; s3.w += v3.w;
        }
        for (; u < e; ++u) {
            float4 v0 = ldcs4(base + (size_t)u * HH);
            s0.x += v0.x; s0.y += v0.y; s0.z += v0.z; s0.w += v0.w;
        }
        const float inv = 1.0f / (float)(e - t);
        __half2* p = reinterpret_cast<__half2*>(g_a + obase + (size_t)w * HH);
        p[0] = __halves2half2(__float2half_rn((s0.x + s1.x + s2.x + s3.x) * inv),
                              __float2half_rn((s0.y + s1.y + s2.y + s3.y) * inv));
        p[1] = __halves2half2(__float2half_rn((s0.z + s1.z + s2.z + s3.z) * inv),
                              __float2half_rn((s0.w + s1.w + s2.w + s3.w) * inv));
        present |= 1u << (w - w0);
        t = e;
    }
#pragma unroll
    for (int wl = 0; wl < WPB; ++wl) {
        if (!(present & (1u << wl))) {
            __half2 z = __halves2half2(__float2half_rn(0.f), __float2half_rn(0.f));
            __half2* p = reinterpret_cast<__half2*>(g_a + obase + (size_t)(w0 + wl) * HH);
            p[0] = z; p[1] = z;
        }
    }
}

// ---------------------------------------------------------------------------
// HMMA GEMM (R16 + unrolled stage slots + smem bias).
// CTA 128x128, BK=32, 4-stage cp.async, 8 warps (2x4), warp tile 64x32.
// 2 CTAs / SM (64.5 KB smem each, <=128 regs) = 16 warps/SM.
// ---------------------------------------------------------------------------
#define BM 128
#define BN 128
#define BK 32
#define KTILES   (HH / BK)     // 24
#define STAGES   4
#define OFF_A    0             // [128][32] fp16 = 8 KB (64B rows)
#define OFF_B    8192          // [32][128] fp16 = 8 KB (256B rows)
#define STAGE_B  16384
#define OFF_BIAS (STAGES * STAGE_B)          // 65536
#define SMEM_TOTAL (OFF_BIAS + BN * 4)       // 66048

__device__ __forceinline__ uint32_t swA(uint32_t off) { return off ^ ((off >> 3) & 0x30); }
__device__ __forceinline__ uint32_t swB(uint32_t off) { return off ^ ((off >> 4) & 0x70); }

__global__ __launch_bounds__(256, 2)
void mma_gemm_kernel(const float* __restrict__ bias, float* __restrict__ C) {
    extern __shared__ char smem[];
    const uint32_t sb = smem_u32(smem);
    const int tid  = threadIdx.x;
    const int lane = tid & 31;
    const int wid  = tid >> 5;
    const int bm = blockIdx.y * BM;
    const int bn = blockIdx.x * BN;
    const int wm = (wid >> 2) * 64;   // 0 / 64
    const int wn = (wid & 3) * 32;    // 0..96

    // stage bias tile into smem (read in epilogue via LDS)
    if (tid < BN / 4) {
        float4 bv = *reinterpret_cast<const float4*>(bias + bn + tid * 4);
        *reinterpret_cast<float4*>(smem + OFF_BIAS + tid * 16) = bv;
    }

    float acc[4][4][4];
#pragma unroll
    for (int i = 0; i < 4; ++i)
#pragma unroll
        for (int j = 0; j < 4; ++j)
#pragma unroll
            for (int q = 0; q < 4; ++q) acc[i][j][q] = 0.0f;

    auto load_stage = [&](int slot, int kt) {
        const uint32_t st = sb + slot * STAGE_B;
        const size_t ka = (size_t)kt * BK;
#pragma unroll
        for (int it = 0; it < 2; ++it) {
            int p = tid + it * 256;
            int m = p >> 2, u = p & 3;
            cp16(st + OFF_A + swA((uint32_t)m * 64 + u * 16),
                 g_a + (size_t)(bm + m) * HH + ka + u * 8);
        }
#pragma unroll
        for (int it = 0; it < 2; ++it) {
            int p = tid + it * 256;
            int k = p >> 4, u = p & 15;
            cp16(st + OFF_B + swB((uint32_t)k * 256 + u * 16),
                 g_w + (size_t)(ka + k) * VV + bn + u * 8);
        }
        asm volatile("cp.async.commit_group;");
    };

#pragma unroll
    for (int s = 0; s < STAGES - 1; ++s) load_stage(s, s);

    for (int ko = 0; ko < KTILES; ko += STAGES) {
#pragma unroll
        for (int sl = 0; sl < STAGES; ++sl) {
            const int kt = ko + sl;
            asm volatile("cp.async.wait_group 2;");
            __syncthreads();
            const uint32_t st = sb + sl * STAGE_B;   // compile-time slot

#pragma unroll
            for (int h = 0; h < 2; ++h) {
                const int k16 = h * 16;
                uint32_t af[4][4];
                uint32_t bf[2][4];
                // first mma (af[0], bf[0]) operands first, then the rest
                {
                    uint32_t row = wm + 0 * 16 + (lane & 15);
                    uint32_t u = (uint32_t)(k16 >> 3) + (lane >> 4);
                    ldsm4(af[0], st + OFF_A + swA(row * 64 + u * 16));
                }
                {
                    uint32_t bk = (uint32_t)k16 + (lane & 15);
                    uint32_t u = (uint32_t)(wn >> 3) + (lane >> 4);
                    ldsm4t(bf[0], st + OFF_B + swB(bk * 256 + u * 16));
                    ldsm4t(bf[1], st + OFF_B + swB(bk * 256 + u * 16 + 32));
                }
#pragma unroll
                for (int i = 1; i < 4; ++i) {
                    uint32_t row = wm + i * 16 + (lane & 15);
                    uint32_t u = (uint32_t)(k16 >> 3) + (lane >> 4);
                    ldsm4(af[i], st + OFF_A + swA(row * 64 + u * 16));
                }
#pragma unroll
                for (int i = 0; i < 4; ++i) {
                    mma_f16(acc[i][0], af[i], bf[0]);
                    mma_f16(acc[i][1], af[i], bf[0] + 2);
                    mma_f16(acc[i][2], af[i], bf[1]);
                    mma_f16(acc[i][3], af[i], bf[1] + 2);
                }
            }
            if (kt + STAGES - 1 < KTILES)
                load_stage((sl + STAGES - 1) & (STAGES - 1), kt + STAGES - 1);
            else
                asm volatile("cp.async.commit_group;");
        }
    }

    // ---- epilogue: smem bias + streaming store ----
    const int rbase = bm + wm + (lane >> 2);
    const int cloc  = wn + (lane & 3) * 2;
#pragma unroll
    for (int j = 0; j < 4; ++j) {
        const int cl = cloc + j * 8;
        float2 bv = *reinterpret_cast<const float2*>(smem + OFF_BIAS + cl * 4);
        const int c = bn + cl;
#pragma unroll
        for (int i = 0; i < 4; ++i) {
            const int r = rbase + i * 16;
            stcs2(&C[(size_t)r * VV + c],
                  make_float2(acc[i][j][0] + bv.x, acc[i][j][1] + bv.y));
            stcs2(&C[(size_t)(r + 8) * VV + c],
                  make_float2(acc[i][j][2] + bv.x, acc[i][j][3] + bv.y));
        }
    }
}

// ---------------------------------------------------------------------------
// Launch
// ---------------------------------------------------------------------------
extern "C" void kernel_launch(void* const* d_in, const int* in_sizes, int n_in,
                              void* d_out, int out_size) {
    const float* enc  = (const float*)d_in[0];   // [32,512,768]
    const int*   ids  = (const int*)  d_in[1];   // [32,512]
    const float* W    = (const float*)d_in[2];   // [768,8192]
    const float* bias = (const float*)d_in[3];   // [8192]
    float* out = (float*)d_out;                  // [32,256,8192]

    prep_kernel<<<SEG_BLOCKS + WC_BLOCKS, 192>>>(enc, ids, W);

    cudaFuncSetAttribute(mma_gemm_kernel,
                         cudaFuncAttributeMaxDynamicSharedMemorySize, SMEM_TOTAL);
    mma_gemm_kernel<<<dim3(VV / BN, MM / BM), 256, SMEM_TOTAL>>>(bias, out);
}